// round 11
// baseline (speedup 1.0000x reference)
#include <cuda_runtime.h>

// out[p, :] = cumsum(W, axis=1)[:, x[p]] + b, p in [0, 8192*200)
// x: int32 (NPOS), W: fp32 (64,129) row-major, b: fp32 (64), out: fp32 (NPOS*64)

#define F1 129                  // num_feature + 1
#define D  64                   // vector dim
#define NPOS (8192 * 200)       // 1,638,400 positions (divisible by 32)
#define TPB 256
#define WARPS_PB (TPB / 32)

// Lookup table in global memory (L1-resident during gather):
// g_table[c*D + d] = b[d] + sum_{j<=c} W[d*F1 + j]
// Every CTA rebuilds it redundantly each launch; all writers produce
// bit-identical values, so the cross-CTA race is value-benign.
__device__ float g_table[F1 * D];

__global__ void __launch_bounds__(TPB, 8)
embed_kernel(const int* __restrict__ x,
             const float* __restrict__ W,
             const float* __restrict__ b,
             float* __restrict__ out) {
    __shared__ float carry[4][D];          // 1 KB: per-segment sums only

    // ---- in-CTA table build: 256 threads = 4 segments x 64 dims ----
    {
        const int t   = threadIdx.x;
        const int d   = t & 63;
        const int seg = t >> 6;                 // 0..3
        const int start = seg * 33;             // 0,33,66,99
        const int cnt   = (seg == 3) ? 30 : 33;
        const float* wrow = W + d * F1 + start;

        // Pass 1: segment sum (batched loads -> one memory round-trip)
        float s = 0.f;
        int j = 0;
        for (; j + 8 <= cnt; j += 8) {
            float v[8];
            #pragma unroll
            for (int u = 0; u < 8; ++u) v[u] = __ldg(&wrow[j + u]);
            #pragma unroll
            for (int u = 0; u < 8; ++u) s += v[u];
        }
        for (; j < cnt; ++j) s += __ldg(&wrow[j]);
        carry[seg][d] = s;
        __syncthreads();

        // Pass 2: carry-in, then prefix chain (W now L1-hot; loads
        // prefetched in batches, chain is FADD-bound)
        float p = __ldg(&b[d]);
        #pragma unroll
        for (int q = 0; q < 3; ++q)
            if (q < seg) p += carry[q][d];

        j = 0;
        for (; j + 8 <= cnt; j += 8) {
            float v[8];
            #pragma unroll
            for (int u = 0; u < 8; ++u) v[u] = __ldg(&wrow[j + u]);
            #pragma unroll
            for (int u = 0; u < 8; ++u) {
                p += v[u];
                g_table[(start + j + u) * D + d] = p;   // warp-contiguous 128B
            }
        }
        for (; j < cnt; ++j) {
            p += __ldg(&wrow[j]);
            g_table[(start + j) * D + d] = p;
        }
        __syncthreads();   // CTA-scope fence: table writes visible to CTA reads
    }

    // ---- gather/store loop: identical to the 71.3us best (R9) ----
    const float4* __restrict__ gt4 = reinterpret_cast<const float4*>(g_table);

    const int lane   = threadIdx.x & 31;
    const int lane15 = lane & 15;          // which float4 within the 64-float row
    const int half   = lane >> 4;          // 0/1: which of each pair of positions
    const int warp   = threadIdx.x >> 5;

    const int gwarp  = blockIdx.x * WARPS_PB + warp;
    const int nwarps = gridDim.x * WARPS_PB;
    const int stride = nwarps * 32;
    float4* __restrict__ o4 = reinterpret_cast<float4*>(out);

    #pragma unroll 1
    for (int base = gwarp * 32; base < NPOS; base += stride) {
        // x read once: evict-first so it never displaces the table in L1
        const int xv = __ldcs(&x[base + lane]);        // coalesced 128B

        // warp covers 32 consecutive positions; store addrs = wbase + k*512B
        float4* wbase = o4 + ((size_t)base + half) * (D / 4) + lane15;
        #pragma unroll
        for (int k = 0; k < 16; ++k) {
            const int xi = __shfl_sync(0xffffffffu, xv, 2 * k + half);
            const float4 v = __ldg(&gt4[xi * (D / 4) + lane15]);  // L1 hit
            __stcs(wbase + k * 2 * (D / 4), v);        // streaming store
        }
    }
}

extern "C" void kernel_launch(void* const* d_in, const int* in_sizes, int n_in,
                              void* d_out, int out_size) {
    const int*   x = (const int*)  d_in[0];
    const float* W = (const float*)d_in[1];
    const float* b = (const float*)d_in[2];
    float*     out = (float*)d_out;

    // Single node: 152 SMs * 8 CTAs of 256 threads (64 warps/SM, no table smem)
    const int grid = 152 * 8;
    embed_kernel<<<grid, TPB>>>(x, W, b, out);
}

// round 12
// speedup vs baseline: 1.0557x; 1.0557x over previous
#include <cuda_runtime.h>

// out[p, :] = cumsum(W, axis=1)[:, x[p]] + b, p in [0, 8192*200)
// x: int32 (NPOS), W: fp32 (64,129) row-major, b: fp32 (64), out: fp32 (NPOS*64)

#define F1 129                  // num_feature + 1
#define D  64                   // vector dim
#define NPOS (8192 * 200)       // 1,638,400 positions (divisible by 32)
#define TPB 256
#define WARPS_PB (TPB / 32)
#define NREP 152                // one table replica per SM (grid = 152*8)

// Per-SM table replicas: g_tables[r][c*D + d] = b[d] + sum_{j<=c} W[d*F1 + j]
// CTAs with the same (blockIdx.x % 152) share a replica; contiguous-modular
// CTA->SM placement puts them on the same SM, so each SM's L1 holds one
// replica. Writers of a replica produce bit-identical values (benign race).
__device__ float g_tables[NREP][F1 * D];

__global__ void __launch_bounds__(TPB, 8)
embed_kernel(const int* __restrict__ x,
             const float* __restrict__ W,
             const float* __restrict__ b,
             float* __restrict__ out) {
    __shared__ float carry[4][D];          // 1 KB: per-segment sums only

    float* __restrict__ tab = g_tables[blockIdx.x % NREP];

    // ---- in-CTA table build: 256 threads = 4 segments x 64 dims ----
    {
        const int t   = threadIdx.x;
        const int d   = t & 63;
        const int seg = t >> 6;                 // 0..3
        const int start = seg * 33;             // 0,33,66,99
        const int cnt   = (seg == 3) ? 30 : 33;
        const float* wrow = W + d * F1 + start;

        // Pass 1: segment sum (batched loads -> one memory round-trip)
        float s = 0.f;
        int j = 0;
        for (; j + 8 <= cnt; j += 8) {
            float v[8];
            #pragma unroll
            for (int u = 0; u < 8; ++u) v[u] = __ldg(&wrow[j + u]);
            #pragma unroll
            for (int u = 0; u < 8; ++u) s += v[u];
        }
        for (; j < cnt; ++j) s += __ldg(&wrow[j]);
        carry[seg][d] = s;
        __syncthreads();

        // Pass 2: carry-in, then prefix chain (W now L1-hot)
        float p = __ldg(&b[d]);
        #pragma unroll
        for (int q = 0; q < 3; ++q)
            if (q < seg) p += carry[q][d];

        j = 0;
        for (; j + 8 <= cnt; j += 8) {
            float v[8];
            #pragma unroll
            for (int u = 0; u < 8; ++u) v[u] = __ldg(&wrow[j + u]);
            #pragma unroll
            for (int u = 0; u < 8; ++u) {
                p += v[u];
                tab[(start + j + u) * D + d] = p;   // warp-contiguous 128B
            }
        }
        for (; j < cnt; ++j) {
            p += __ldg(&wrow[j]);
            tab[(start + j) * D + d] = p;
        }
        __syncthreads();   // CTA's own table writes visible to CTA reads
    }

    // ---- gather/store loop: identical to the 71.3us best (R9) ----
    const float4* __restrict__ gt4 = reinterpret_cast<const float4*>(tab);

    const int lane   = threadIdx.x & 31;
    const int lane15 = lane & 15;          // which float4 within the 64-float row
    const int half   = lane >> 4;          // 0/1: which of each pair of positions
    const int warp   = threadIdx.x >> 5;

    const int gwarp  = blockIdx.x * WARPS_PB + warp;
    const int nwarps = gridDim.x * WARPS_PB;
    const int stride = nwarps * 32;
    float4* __restrict__ o4 = reinterpret_cast<float4*>(out);

    #pragma unroll 1
    for (int base = gwarp * 32; base < NPOS; base += stride) {
        // x read once: evict-first so it never displaces the table in L1
        const int xv = __ldcs(&x[base + lane]);        // coalesced 128B

        // warp covers 32 consecutive positions; store addrs = wbase + k*512B
        float4* wbase = o4 + ((size_t)base + half) * (D / 4) + lane15;
        #pragma unroll
        for (int k = 0; k < 16; ++k) {
            const int xi = __shfl_sync(0xffffffffu, xv, 2 * k + half);
            const float4 v = __ldg(&gt4[xi * (D / 4) + lane15]);  // L1 hit
            __stcs(wbase + k * 2 * (D / 4), v);        // streaming store
        }
    }
}

extern "C" void kernel_launch(void* const* d_in, const int* in_sizes, int n_in,
                              void* d_out, int out_size) {
    const int*   x = (const int*)  d_in[0];
    const float* W = (const float*)d_in[1];
    const float* b = (const float*)d_in[2];
    float*     out = (float*)d_out;

    // Single node: 152 SMs * 8 CTAs of 256 threads (64 warps/SM, 1KB smem)
    const int grid = NREP * 8;
    embed_kernel<<<grid, TPB>>>(x, W, b, out);
}